// round 3
// baseline (speedup 1.0000x reference)
#include <cuda_runtime.h>
#include <math_constants.h>

#define C       384
#define DH      64
#define CTXC    128
#define BT      10
#define TFRAMES 5
#define NSTG    4
#define QSCALE  0.125f
#define NWARPS  12            // 384 / 32

// hw per stage: 6400, 1600, 400, 100 ; 10*hw cumulative: 0,64000,80000,84000,85000
#define NPIX_TOTAL  85000
#define NPIX2_TOTAL 42500     // pixel pairs
#define VOUT_TOTAL  32640000  // 10*384*8500

__constant__ int c_hw[NSTG]       = {6400, 1600, 400, 100};
__constant__ int c_hw2[NSTG]      = {3200, 800, 200, 50};
__constant__ int c_pixoff[NSTG]   = {0, 64000, 80000, 84000};
__constant__ int c_pixoff2[NSTG]  = {0, 32000, 40000, 42000};
__constant__ int c_voutoff[NSTG]  = {0, 24576000, 30720000, 32256000};

__device__ float g_wq  [NSTG * BT * C];
__device__ float g_y   [NSTG * BT * C];
__device__ float g_xbar[NSTG * BT * C];
__device__ float g_sim [NPIX_TOTAL];

__device__ __forceinline__ float warp_sum(float v) {
    #pragma unroll
    for (int o = 16; o > 0; o >>= 1) v += __shfl_down_sync(0xffffffffu, v, o);
    return v;
}

// ---------------------------------------------------------------------------
// K1: per-(stage, b) small algebra — warp-per-output-row (coalesced weights).
//   a    = Wp @ audio + bp                       [C]
//   cqk  = Wcqk @ (a + pe[t])                    [DH]
//   cv   = Wcv  @ a                              [DH]
//   y    = Wo @ cv + bo      (vout broadcast)    [C]
//   wq   = SCALE * (cqk @ Wqk)                   [C]
// ---------------------------------------------------------------------------
__global__ __launch_bounds__(C)
void k_setup(const float* __restrict__ a0, const float* __restrict__ a1,
             const float* __restrict__ a2, const float* __restrict__ a3,
             const float* __restrict__ ctx_proj_w, const float* __restrict__ ctx_proj_b,
             const float* __restrict__ pos_emb,
             const float* __restrict__ qk_w, const float* __restrict__ ctx_qk_w,
             const float* __restrict__ ctx_v_w,
             const float* __restrict__ out_w, const float* __restrict__ out_b)
{
    int s = blockIdx.x / BT;
    int b = blockIdx.x % BT;
    const float* audio = (s == 0 ? a0 : s == 1 ? a1 : s == 2 ? a2 : a3) + b * CTXC;

    __shared__ float sh_au[CTXC];
    __shared__ float sh_a[C];
    __shared__ float sh_cqk[DH];
    __shared__ float sh_cv[DH];

    const int tid  = threadIdx.x;
    const int lane = tid & 31;
    const int warp = tid >> 5;

    if (tid < CTXC) sh_au[tid] = audio[tid];
    __syncthreads();

    // a[c] : warp-per-c, lanes over CTXC (coalesced weight rows)
    for (int c = warp; c < C; c += NWARPS) {
        const float* wp = ctx_proj_w + ((size_t)s * C + c) * CTXC;
        float acc = 0.f;
        #pragma unroll
        for (int k = lane; k < CTXC; k += 32) acc += wp[k] * sh_au[k];
        acc = warp_sum(acc);
        if (lane == 0) sh_a[c] = acc + ctx_proj_b[s * C + c];
    }
    __syncthreads();

    // cqk[d], cv[d] : warp-per-d, lanes over C
    const float* pe = pos_emb + ((size_t)s * TFRAMES + (b % TFRAMES)) * C;
    for (int d = warp; d < DH; d += NWARPS) {
        const float* wcqk = ctx_qk_w + ((size_t)s * DH + d) * C;
        const float* wcv  = ctx_v_w  + ((size_t)s * DH + d) * C;
        float s1 = 0.f, s2 = 0.f;
        #pragma unroll
        for (int j = lane; j < C; j += 32) {
            float av = sh_a[j];
            s1 += wcqk[j] * (av + pe[j]);
            s2 += wcv[j] * av;
        }
        s1 = warp_sum(s1);
        s2 = warp_sum(s2);
        if (lane == 0) { sh_cqk[d] = s1; sh_cv[d] = s2; }
    }
    __syncthreads();

    // y[c] = Wo @ cv + bo : warp-per-c, lanes over DH
    for (int c = warp; c < C; c += NWARPS) {
        const float* wo = out_w + ((size_t)s * C + c) * DH;
        float acc = 0.f;
        #pragma unroll
        for (int d = lane; d < DH; d += 32) acc += wo[d] * sh_cv[d];
        acc = warp_sum(acc);
        if (lane == 0) g_y[(s * BT + b) * C + c] = acc + out_b[s * C + c];
    }

    // wq[c] : thread-per-c (qk_w[d*C + c] is coalesced across threads)
    {
        float wv = 0.f;
        const float* wqk = qk_w + (size_t)s * DH * C + tid;
        #pragma unroll 8
        for (int d = 0; d < DH; d++) wv += sh_cqk[d] * wqk[(size_t)d * C];
        g_wq[(s * BT + b) * C + tid] = wv * QSCALE;
    }
}

// ---------------------------------------------------------------------------
// K2: one thread per pixel PAIR (float2 path).
//   sim[i]    = sum_c (x[b,c,i] + pos[b,c,i]) * wq[s,b,c]
//   vout[...] = y[s,b,c]  (broadcast, fused)
// ---------------------------------------------------------------------------
__global__ __launch_bounds__(256)
void k_sim_vout(const float* __restrict__ x0, const float* __restrict__ x1,
                const float* __restrict__ x2, const float* __restrict__ x3,
                const float* __restrict__ p0, const float* __restrict__ p1,
                const float* __restrict__ p2, const float* __restrict__ p3,
                float* __restrict__ out)
{
    int g = blockIdx.x * blockDim.x + threadIdx.x;
    if (g >= NPIX2_TOTAL) return;

    int s;
    if      (g < 32000) s = 0;
    else if (g < 40000) s = 1;
    else if (g < 42000) s = 2;
    else                s = 3;

    const int hw    = c_hw[s];
    const int hw2   = c_hw2[s];
    const int local = g - c_pixoff2[s];
    const int b     = local / hw2;
    const int i     = (local - b * hw2) * 2;

    const float* x = (s == 0 ? x0 : s == 1 ? x1 : s == 2 ? x2 : x3);
    const float* p = (s == 0 ? p0 : s == 1 ? p1 : s == 2 ? p2 : p3);

    const float* xb = x + ((size_t)b * C) * hw + i;
    const float* pb = p + ((size_t)b * C) * hw + i;
    const float* wq = g_wq + (s * BT + b) * C;
    const float* yv = g_y  + (s * BT + b) * C;
    float* vout = out + c_voutoff[s] + ((size_t)b * C) * hw + i;

    float a0 = 0.f, a1 = 0.f;
    #pragma unroll 4
    for (int c = 0; c < C; c++) {
        float2 xv = *(const float2*)(xb + (size_t)c * hw);
        float2 pv = *(const float2*)(pb + (size_t)c * hw);
        float  wc = wq[c];
        a0 = fmaf(xv.x + pv.x, wc, a0);
        a1 = fmaf(xv.y + pv.y, wc, a1);
        float yc = yv[c];
        *(float2*)(vout + (size_t)c * hw) = make_float2(yc, yc);
    }
    int gp = c_pixoff[s] + b * hw + i;
    g_sim[gp]     = a0;
    g_sim[gp + 1] = a1;
}

// ---------------------------------------------------------------------------
// K3: xbar[s,b,c] = sum_i softmax_i(sim[s,b,:]) * x[b,c,i]
// Block per (stage, b, channel-group of 16): recompute softmax into smem,
// then 8 warps x 2 channels, float2 accumulation.
// ---------------------------------------------------------------------------
#define CG        16
#define NGROUPS   (C / CG)          // 24
#define XBAR_THREADS 256

__global__ __launch_bounds__(XBAR_THREADS)
void k_xbar(const float* __restrict__ x0, const float* __restrict__ x1,
            const float* __restrict__ x2, const float* __restrict__ x3)
{
    int blk = blockIdx.x;
    int grp = blk % NGROUPS;
    int sb  = blk / NGROUPS;
    int s   = sb / BT;
    int b   = sb % BT;
    const int hw = c_hw[s];

    const float* sim = g_sim + c_pixoff[s] + b * hw;

    __shared__ float sh_p[6400];
    __shared__ float sh_red[8];
    __shared__ float sh_bc[2];

    const int tid  = threadIdx.x;
    const int lane = tid & 31;
    const int warp = tid >> 5;

    // --- max reduce ---
    float m = -CUDART_INF_F;
    for (int i = tid; i < hw; i += XBAR_THREADS) m = fmaxf(m, sim[i]);
    #pragma unroll
    for (int o = 16; o > 0; o >>= 1) m = fmaxf(m, __shfl_down_sync(0xffffffffu, m, o));
    if (lane == 0) sh_red[warp] = m;
    __syncthreads();
    if (tid < 8) {
        float v = sh_red[tid];
        #pragma unroll
        for (int o = 4; o > 0; o >>= 1) v = fmaxf(v, __shfl_down_sync(0xffu, v, o));
        if (tid == 0) sh_bc[0] = v;
    }
    __syncthreads();
    m = sh_bc[0];

    // --- exp + sum reduce, store p ---
    float ssum = 0.f;
    for (int i = tid; i < hw; i += XBAR_THREADS) {
        float e = __expf(sim[i] - m);
        sh_p[i] = e;
        ssum += e;
    }
    ssum = warp_sum(ssum);
    if (lane == 0) sh_red[warp] = ssum;
    __syncthreads();
    if (tid < 8) {
        float v = sh_red[tid];
        #pragma unroll
        for (int o = 4; o > 0; o >>= 1) v += __shfl_down_sync(0xffu, v, o);
        if (tid == 0) sh_bc[1] = 1.f / v;
    }
    __syncthreads();
    const float rinv = sh_bc[1];

    const float* x = (s == 0 ? x0 : s == 1 ? x1 : s == 2 ? x2 : x3);

    // 8 warps * 2 channels each = 16 channels ; float2 loads (hw always even)
    #pragma unroll
    for (int cc = 0; cc < 2; cc++) {
        int c = grp * CG + warp * 2 + cc;
        const float* xc = x + ((size_t)b * C + c) * hw;
        float acc0 = 0.f, acc1 = 0.f;
        for (int i = lane * 2; i < hw; i += 64) {
            float2 xv = *(const float2*)(xc + i);
            acc0 = fmaf(sh_p[i],     xv.x, acc0);
            acc1 = fmaf(sh_p[i + 1], xv.y, acc1);
        }
        float acc = warp_sum(acc0 + acc1);
        if (lane == 0) g_xbar[(s * BT + b) * C + c] = acc * rinv;
    }
}

// ---------------------------------------------------------------------------
// K4: aout[s,b,c] = ctx_out_b + Wco @ (Wv @ xbar) — warp-per-output-row.
// ---------------------------------------------------------------------------
__global__ __launch_bounds__(C)
void k_aout(const float* __restrict__ v_w,
            const float* __restrict__ ctx_out_w,
            const float* __restrict__ ctx_out_b,
            float* __restrict__ out)
{
    int s = blockIdx.x / BT;
    int b = blockIdx.x % BT;
    __shared__ float sh_xb[C];
    __shared__ float sh_t[DH];

    const int tid  = threadIdx.x;
    const int lane = tid & 31;
    const int warp = tid >> 5;

    sh_xb[tid] = g_xbar[(s * BT + b) * C + tid];
    __syncthreads();

    // t[d] = Wv[d,:] @ xbar : warp-per-d, lanes over C (coalesced)
    for (int d = warp; d < DH; d += NWARPS) {
        const float* wv = v_w + ((size_t)s * DH + d) * C;
        float acc = 0.f;
        #pragma unroll
        for (int j = lane; j < C; j += 32) acc += wv[j] * sh_xb[j];
        acc = warp_sum(acc);
        if (lane == 0) sh_t[d] = acc;
    }
    __syncthreads();

    // aout[c] = Wco[c,:] @ t + bco : warp-per-c, lanes over DH (coalesced)
    for (int c = warp; c < C; c += NWARPS) {
        const float* wco = ctx_out_w + ((size_t)s * C + c) * DH;
        float acc = 0.f;
        #pragma unroll
        for (int d = lane; d < DH; d += 32) acc += wco[d] * sh_t[d];
        acc = warp_sum(acc);
        if (lane == 0)
            out[VOUT_TOTAL + (s * BT + b) * C + c] = acc + ctx_out_b[s * C + c];
    }
}

// ---------------------------------------------------------------------------
extern "C" void kernel_launch(void* const* d_in, const int* in_sizes, int n_in,
                              void* d_out, int out_size)
{
    const float *fm[NSTG], *ps[NSTG], *au[NSTG];
    bool dict_order = (in_sizes[1] == in_sizes[0]);
    if (dict_order) {
        for (int s = 0; s < NSTG; s++) {
            fm[s] = (const float*)d_in[3 * s + 0];
            ps[s] = (const float*)d_in[3 * s + 1];
            au[s] = (const float*)d_in[3 * s + 2];
        }
    } else {
        for (int s = 0; s < NSTG; s++) {
            fm[s] = (const float*)d_in[s];
            au[s] = (const float*)d_in[4 + s];
            ps[s] = (const float*)d_in[8 + s];
        }
    }
    const float* ctx_proj_w = (const float*)d_in[12];
    const float* ctx_proj_b = (const float*)d_in[13];
    const float* pos_emb    = (const float*)d_in[14];
    const float* qk_w       = (const float*)d_in[15];
    const float* ctx_qk_w   = (const float*)d_in[16];
    const float* v_w        = (const float*)d_in[17];
    const float* ctx_v_w    = (const float*)d_in[18];
    const float* out_w      = (const float*)d_in[19];
    const float* out_b      = (const float*)d_in[20];
    const float* ctx_out_w  = (const float*)d_in[21];
    const float* ctx_out_b  = (const float*)d_in[22];

    float* out = (float*)d_out;

    k_setup<<<NSTG * BT, C>>>(au[0], au[1], au[2], au[3],
                              ctx_proj_w, ctx_proj_b, pos_emb,
                              qk_w, ctx_qk_w, ctx_v_w, out_w, out_b);

    k_sim_vout<<<(NPIX2_TOTAL + 255) / 256, 256>>>(fm[0], fm[1], fm[2], fm[3],
                                                   ps[0], ps[1], ps[2], ps[3], out);

    k_xbar<<<NSTG * BT * NGROUPS, XBAR_THREADS>>>(fm[0], fm[1], fm[2], fm[3]);

    k_aout<<<NSTG * BT, C>>>(v_w, ctx_out_w, ctx_out_b, out);
}

// round 4
// speedup vs baseline: 2.5399x; 2.5399x over previous
#include <cuda_runtime.h>
#include <math_constants.h>

#define C       384
#define DH      64
#define CTXC    128
#define BT      10
#define TFRAMES 5
#define NSTG    4
#define QSCALE  0.125f

// hw per stage: 6400, 1600, 400, 100
#define NPIX_TOTAL  85000          // sum of 10*hw
#define NQUAD_TOTAL 21250          // pixel quads
#define NCHUNK      4
#define CCHUNK      96             // 384 / 4
#define NUNITS      85000          // NQUAD_TOTAL * NCHUNK
#define VOUT_TOTAL  32640000       // 10*384*8500

__constant__ int c_hw[NSTG]      = {6400, 1600, 400, 100};
__constant__ int c_hw4[NSTG]     = {1600, 400, 100, 25};
__constant__ int c_pixoff[NSTG]  = {0, 64000, 80000, 84000};
__constant__ int c_qoff[NSTG]    = {0, 16000, 20000, 21000};
__constant__ int c_voutoff[NSTG] = {0, 24576000, 30720000, 32256000};

__device__ float g_wq  [NSTG * BT * C];
__device__ float g_y   [NSTG * BT * C];
__device__ float g_xbar[NSTG * BT * C];
__device__ float g_sim [NPIX_TOTAL];
__device__ float g_simp[NCHUNK * NPIX_TOTAL];

__device__ __forceinline__ float4 ld4(const float* p) { return *(const float4*)p; }

// ---------------------------------------------------------------------------
// K1: per-(stage,b) small algebra. Row-segment-per-thread: every thread issues
// a contiguous run of float4 loads (high MLP), partials combined via smem.
// ---------------------------------------------------------------------------
__global__ __launch_bounds__(C)
void k_setup(const float* __restrict__ a0, const float* __restrict__ a1,
             const float* __restrict__ a2, const float* __restrict__ a3,
             const float* __restrict__ ctx_proj_w, const float* __restrict__ ctx_proj_b,
             const float* __restrict__ pos_emb,
             const float* __restrict__ qk_w, const float* __restrict__ ctx_qk_w,
             const float* __restrict__ ctx_v_w,
             const float* __restrict__ out_w, const float* __restrict__ out_b)
{
    int s = blockIdx.x / BT;
    int b = blockIdx.x % BT;
    const float* audio = (s == 0 ? a0 : s == 1 ? a1 : s == 2 ? a2 : a3) + b * CTXC;

    __shared__ float sh_au[CTXC];
    __shared__ float sh_a[C];      // a
    __shared__ float sh_ap[C];     // a + pe
    __shared__ float sh_part[128 * 3];
    __shared__ float sh_cqk[DH];
    __shared__ float sh_cv[DH];

    const int tid = threadIdx.x;

    if (tid < CTXC) sh_au[tid] = audio[tid];
    __syncthreads();

    // --- a[c] = Wp[c,:] @ audio + bp : thread-per-c, 32 float4 contiguous ---
    {
        const float* wp = ctx_proj_w + ((size_t)s * C + tid) * CTXC;
        float acc = 0.f;
        #pragma unroll
        for (int k = 0; k < CTXC; k += 4) {
            float4 w = ld4(wp + k);
            float4 u = ld4(sh_au + k);
            acc += w.x * u.x + w.y * u.y + w.z * u.z + w.w * u.w;
        }
        float av = acc + ctx_proj_b[s * C + tid];
        sh_a[tid]  = av;
        sh_ap[tid] = av + pos_emb[((size_t)s * TFRAMES + (b % TFRAMES)) * C + tid];
    }
    __syncthreads();

    // --- cqk[d] = Wcqk[d,:] @ (a+pe), cv[d] = Wcv[d,:] @ a ---
    // unit t = chunk*128 + m*64 + d  (chunk in [0,3), m = matrix, d = row)
    {
        int chunk = tid >> 7;          // /128
        int r     = tid & 127;
        int m     = r >> 6;
        int d     = r & 63;
        const float* wrow = (m == 0 ? ctx_qk_w : ctx_v_w) + ((size_t)s * DH + d) * C + chunk * 128;
        const float* vec  = (m == 0 ? sh_ap : sh_a) + chunk * 128;
        float acc = 0.f;
        #pragma unroll
        for (int k = 0; k < 128; k += 4) {
            float4 w = ld4(wrow + k);
            float4 u = ld4(vec + k);
            acc += w.x * u.x + w.y * u.y + w.z * u.z + w.w * u.w;
        }
        sh_part[(m * 64 + d) * 3 + chunk] = acc;
    }
    __syncthreads();
    if (tid < 128) {
        float v = (sh_part[tid * 3 + 0] + sh_part[tid * 3 + 1]) + sh_part[tid * 3 + 2];
        if (tid < 64) sh_cqk[tid] = v; else sh_cv[tid - 64] = v;
    }
    __syncthreads();

    // --- y[c] = Wo[c,:] @ cv + bo : thread-per-c, 16 float4 contiguous ---
    {
        const float* wo = out_w + ((size_t)s * C + tid) * DH;
        float acc = 0.f;
        #pragma unroll
        for (int d = 0; d < DH; d += 4) {
            float4 w = ld4(wo + d);
            float4 t = ld4(sh_cv + d);
            acc += w.x * t.x + w.y * t.y + w.z * t.z + w.w * t.w;
        }
        g_y[(s * BT + b) * C + tid] = acc + out_b[s * C + tid];
    }

    // --- wq[c] = QSCALE * sum_d cqk[d] * Wqk[d,c] : coalesced over c ---
    {
        float wv = 0.f;
        const float* wqk = qk_w + (size_t)s * DH * C + tid;
        #pragma unroll 16
        for (int d = 0; d < DH; d++) wv += sh_cqk[d] * wqk[(size_t)d * C];
        g_wq[(s * BT + b) * C + tid] = wv * QSCALE;
    }
}

// ---------------------------------------------------------------------------
// K2: unit = (c-chunk of 96, pixel-quad). float4 loads/stores, 85000 threads.
//   simp[chunk][i..i+3] += (x+pos)·wq over the chunk ; vout = y broadcast.
// ---------------------------------------------------------------------------
__global__ __launch_bounds__(256)
void k_sim_vout(const float* __restrict__ x0, const float* __restrict__ x1,
                const float* __restrict__ x2, const float* __restrict__ x3,
                const float* __restrict__ p0, const float* __restrict__ p1,
                const float* __restrict__ p2, const float* __restrict__ p3,
                float* __restrict__ out)
{
    int u = blockIdx.x * blockDim.x + threadIdx.x;
    if (u >= NUNITS) return;

    int chunk = u / NQUAD_TOTAL;
    int q     = u - chunk * NQUAD_TOTAL;

    int s;
    if      (q < 16000) s = 0;
    else if (q < 20000) s = 1;
    else if (q < 21000) s = 2;
    else                s = 3;

    const int hw    = c_hw[s];
    const int hw4   = c_hw4[s];
    const int local = q - c_qoff[s];
    const int b     = local / hw4;
    const int i     = (local - b * hw4) * 4;

    const float* x = (s == 0 ? x0 : s == 1 ? x1 : s == 2 ? x2 : x3);
    const float* p = (s == 0 ? p0 : s == 1 ? p1 : s == 2 ? p2 : p3);

    const int c0 = chunk * CCHUNK;
    const float* xb = x + ((size_t)b * C + c0) * hw + i;
    const float* pb = p + ((size_t)b * C + c0) * hw + i;
    const float* wq = g_wq + (s * BT + b) * C + c0;
    const float* yv = g_y  + (s * BT + b) * C + c0;
    float* vout = out + c_voutoff[s] + ((size_t)b * C + c0) * hw + i;

    float4 acc = make_float4(0.f, 0.f, 0.f, 0.f);
    #pragma unroll 4
    for (int c = 0; c < CCHUNK; c++) {
        float4 xv = ld4(xb + (size_t)c * hw);
        float4 pv = ld4(pb + (size_t)c * hw);
        float  wc = wq[c];
        acc.x = fmaf(xv.x + pv.x, wc, acc.x);
        acc.y = fmaf(xv.y + pv.y, wc, acc.y);
        acc.z = fmaf(xv.z + pv.z, wc, acc.z);
        acc.w = fmaf(xv.w + pv.w, wc, acc.w);
        float yc = yv[c];
        *(float4*)(vout + (size_t)c * hw) = make_float4(yc, yc, yc, yc);
    }
    int gp = c_pixoff[s] + b * hw + i;
    *(float4*)(g_simp + chunk * NPIX_TOTAL + gp) = acc;
}

// ---------------------------------------------------------------------------
// K2b: deterministic fixed-order reduction of the 4 chunk partials.
// ---------------------------------------------------------------------------
__global__ __launch_bounds__(256)
void k_simred()
{
    int g = blockIdx.x * blockDim.x + threadIdx.x;
    if (g >= NPIX_TOTAL) return;
    g_sim[g] = (g_simp[g] + g_simp[NPIX_TOTAL + g]) +
               (g_simp[2 * NPIX_TOTAL + g] + g_simp[3 * NPIX_TOTAL + g]);
}

// ---------------------------------------------------------------------------
// K3: xbar[s,b,c] = sum_i softmax_i(sim[s,b,:]) * x[b,c,i]
// Block per (stage,b,16-channel group); softmax recomputed into smem;
// 8 warps x 2 channels, float4 x loads.
// ---------------------------------------------------------------------------
#define CG        16
#define NGROUPS   (C / CG)          // 24
#define XBAR_THREADS 256

__device__ __forceinline__ float warp_sum(float v) {
    #pragma unroll
    for (int o = 16; o > 0; o >>= 1) v += __shfl_down_sync(0xffffffffu, v, o);
    return v;
}

__global__ __launch_bounds__(XBAR_THREADS)
void k_xbar(const float* __restrict__ x0, const float* __restrict__ x1,
            const float* __restrict__ x2, const float* __restrict__ x3)
{
    int blk = blockIdx.x;
    int grp = blk % NGROUPS;
    int sb  = blk / NGROUPS;
    int s   = sb / BT;
    int b   = sb % BT;
    const int hw = c_hw[s];

    const float* sim = g_sim + c_pixoff[s] + b * hw;

    __shared__ float sh_p[6400];
    __shared__ float sh_red[8];
    __shared__ float sh_bc[2];

    const int tid  = threadIdx.x;
    const int lane = tid & 31;
    const int warp = tid >> 5;

    // --- max ---
    float m = -CUDART_INF_F;
    for (int i = tid; i < hw; i += XBAR_THREADS) m = fmaxf(m, sim[i]);
    #pragma unroll
    for (int o = 16; o > 0; o >>= 1) m = fmaxf(m, __shfl_down_sync(0xffffffffu, m, o));
    if (lane == 0) sh_red[warp] = m;
    __syncthreads();
    if (tid < 8) {
        float v = sh_red[tid];
        #pragma unroll
        for (int o = 4; o > 0; o >>= 1) v = fmaxf(v, __shfl_down_sync(0xffu, v, o));
        if (tid == 0) sh_bc[0] = v;
    }
    __syncthreads();
    m = sh_bc[0];

    // --- exp + sum ---
    float ssum = 0.f;
    for (int i = tid; i < hw; i += XBAR_THREADS) {
        float e = __expf(sim[i] - m);
        sh_p[i] = e;
        ssum += e;
    }
    ssum = warp_sum(ssum);
    if (lane == 0) sh_red[warp] = ssum;
    __syncthreads();
    if (tid < 8) {
        float v = sh_red[tid];
        #pragma unroll
        for (int o = 4; o > 0; o >>= 1) v += __shfl_down_sync(0xffu, v, o);
        if (tid == 0) sh_bc[1] = 1.f / v;
    }
    __syncthreads();
    const float rinv = sh_bc[1];

    const float* x = (s == 0 ? x0 : s == 1 ? x1 : s == 2 ? x2 : x3);

    #pragma unroll
    for (int cc = 0; cc < 2; cc++) {
        int c = grp * CG + warp * 2 + cc;
        const float* xc = x + ((size_t)b * C + c) * hw;
        float a0 = 0.f, a1 = 0.f, a2 = 0.f, a3 = 0.f;
        for (int i = lane * 4; i < hw; i += 128) {
            float4 xv = ld4(xc + i);
            float4 pv = ld4(sh_p + i);
            a0 = fmaf(pv.x, xv.x, a0);
            a1 = fmaf(pv.y, xv.y, a1);
            a2 = fmaf(pv.z, xv.z, a2);
            a3 = fmaf(pv.w, xv.w, a3);
        }
        float acc = warp_sum((a0 + a1) + (a2 + a3));
        if (lane == 0) g_xbar[(s * BT + b) * C + c] = acc * rinv;
    }
}

// ---------------------------------------------------------------------------
// K4: aout[s,b,c] = ctx_out_b + Wco @ (Wv @ xbar).
// Row-segment-per-thread (contiguous float4 runs) + fixed-order smem combine.
// ---------------------------------------------------------------------------
__global__ __launch_bounds__(C)
void k_aout(const float* __restrict__ v_w,
            const float* __restrict__ ctx_out_w,
            const float* __restrict__ ctx_out_b,
            float* __restrict__ out)
{
    int s = blockIdx.x / BT;
    int b = blockIdx.x % BT;
    __shared__ float sh_xb[C];
    __shared__ float sh_part[DH * 6];
    __shared__ float sh_t[DH];

    const int tid = threadIdx.x;

    sh_xb[tid] = g_xbar[(s * BT + b) * C + tid];
    __syncthreads();

    // t[d] partials: unit t = chunk*64 + d, chunk in [0,6), 64-float segments
    {
        int chunk = tid >> 6;
        int d     = tid & 63;
        const float* wv  = v_w + ((size_t)s * DH + d) * C + chunk * 64;
        const float* vec = sh_xb + chunk * 64;
        float acc = 0.f;
        #pragma unroll
        for (int k = 0; k < 64; k += 4) {
            float4 w = ld4(wv + k);
            float4 u = ld4(vec + k);
            acc += w.x * u.x + w.y * u.y + w.z * u.z + w.w * u.w;
        }
        sh_part[d * 6 + chunk] = acc;
    }
    __syncthreads();
    if (tid < DH) {
        const float* p = sh_part + tid * 6;
        sh_t[tid] = ((p[0] + p[1]) + (p[2] + p[3])) + (p[4] + p[5]);
    }
    __syncthreads();

    // aout[c] = Wco[c,:] @ t + bco : thread-per-c, 16 float4 contiguous
    {
        const float* wco = ctx_out_w + ((size_t)s * C + tid) * DH;
        float acc = 0.f;
        #pragma unroll
        for (int d = 0; d < DH; d += 4) {
            float4 w = ld4(wco + d);
            float4 t = ld4(sh_t + d);
            acc += w.x * t.x + w.y * t.y + w.z * t.z + w.w * t.w;
        }
        out[VOUT_TOTAL + (s * BT + b) * C + tid] = acc + ctx_out_b[s * C + tid];
    }
}

// ---------------------------------------------------------------------------
extern "C" void kernel_launch(void* const* d_in, const int* in_sizes, int n_in,
                              void* d_out, int out_size)
{
    const float *fm[NSTG], *ps[NSTG], *au[NSTG];
    bool dict_order = (in_sizes[1] == in_sizes[0]);
    if (dict_order) {
        for (int s = 0; s < NSTG; s++) {
            fm[s] = (const float*)d_in[3 * s + 0];
            ps[s] = (const float*)d_in[3 * s + 1];
            au[s] = (const float*)d_in[3 * s + 2];
        }
    } else {
        for (int s = 0; s < NSTG; s++) {
            fm[s] = (const float*)d_in[s];
            au[s] = (const float*)d_in[4 + s];
            ps[s] = (const float*)d_in[8 + s];
        }
    }
    const float* ctx_proj_w = (const float*)d_in[12];
    const float* ctx_proj_b = (const float*)d_in[13];
    const float* pos_emb    = (const float*)d_in[14];
    const float* qk_w       = (const float*)d_in[15];
    const float* ctx_qk_w   = (const float*)d_in[16];
    const float* v_w        = (const float*)d_in[17];
    const float* ctx_v_w    = (const float*)d_in[18];
    const float* out_w      = (const float*)d_in[19];
    const float* out_b      = (const float*)d_in[20];
    const float* ctx_out_w  = (const float*)d_in[21];
    const float* ctx_out_b  = (const float*)d_in[22];

    float* out = (float*)d_out;

    k_setup<<<NSTG * BT, C>>>(au[0], au[1], au[2], au[3],
                              ctx_proj_w, ctx_proj_b, pos_emb,
                              qk_w, ctx_qk_w, ctx_v_w, out_w, out_b);

    k_sim_vout<<<(NUNITS + 255) / 256, 256>>>(fm[0], fm[1], fm[2], fm[3],
                                              ps[0], ps[1], ps[2], ps[3], out);

    k_simred<<<(NPIX_TOTAL + 255) / 256, 256>>>();

    k_xbar<<<NSTG * BT * NGROUPS, XBAR_THREADS>>>(fm[0], fm[1], fm[2], fm[3]);

    k_aout<<<NSTG * BT, C>>>(v_w, ctx_out_w, ctx_out_b, out);
}

// round 5
// speedup vs baseline: 2.6636x; 1.0487x over previous
#include <cuda_runtime.h>
#include <math_constants.h>

#define C       384
#define DH      64
#define CTXC    128
#define BT      10
#define TFRAMES 5
#define NSTG    4
#define QSCALE  0.125f

// hw per stage: 6400, 1600, 400, 100
#define NPIX_TOTAL  85000          // sum of 10*hw
#define NQUAD_TOTAL 21250          // pixel quads
#define NCHUNK      4
#define CCHUNK      96             // 384 / 4
#define NUNITS      85000          // NQUAD_TOTAL * NCHUNK
#define VOUT_TOTAL  32640000       // 10*384*8500
#define ISEG        1600           // xbar i-segment
#define MAXSEG      4

__constant__ int c_hw[NSTG]      = {6400, 1600, 400, 100};
__constant__ int c_hw4[NSTG]     = {1600, 400, 100, 25};
__constant__ int c_pixoff[NSTG]  = {0, 64000, 80000, 84000};
__constant__ int c_qoff[NSTG]    = {0, 16000, 20000, 21000};
__constant__ int c_voutoff[NSTG] = {0, 24576000, 30720000, 32256000};
__constant__ int c_nseg[NSTG]    = {4, 1, 1, 1};
__constant__ int c_xboff[NSTG]   = {0, 960, 1200, 1440};   // k_xbar block offsets
#define XBAR_BLOCKS 1680

__device__ float g_wq  [NSTG * BT * C];
__device__ float g_y   [NSTG * BT * C];
__device__ float g_xbarp[MAXSEG * NSTG * BT * C];
__device__ float g_p   [NPIX_TOTAL];               // exp(sim - max)
__device__ float g_srinv[NSTG * BT];               // 1 / sum(exp)
__device__ float g_simp[NCHUNK * NPIX_TOTAL];

__device__ __forceinline__ float4 ld4(const float* p) { return *(const float4*)p; }

__device__ __forceinline__ float warp_sum(float v) {
    #pragma unroll
    for (int o = 16; o > 0; o >>= 1) v += __shfl_down_sync(0xffffffffu, v, o);
    return v;
}

// ---------------------------------------------------------------------------
// K1: per-(stage,b) small algebra. Contiguous row-segment-per-thread (MLP),
// fixed-order smem combines.
// ---------------------------------------------------------------------------
__global__ __launch_bounds__(C)
void k_setup(const float* __restrict__ a0, const float* __restrict__ a1,
             const float* __restrict__ a2, const float* __restrict__ a3,
             const float* __restrict__ ctx_proj_w, const float* __restrict__ ctx_proj_b,
             const float* __restrict__ pos_emb,
             const float* __restrict__ qk_w, const float* __restrict__ ctx_qk_w,
             const float* __restrict__ ctx_v_w,
             const float* __restrict__ out_w, const float* __restrict__ out_b)
{
    int s = blockIdx.x / BT;
    int b = blockIdx.x % BT;
    const float* audio = (s == 0 ? a0 : s == 1 ? a1 : s == 2 ? a2 : a3) + b * CTXC;

    __shared__ float sh_au[CTXC];
    __shared__ float sh_a[C];      // a
    __shared__ float sh_ap[C];     // a + pe
    __shared__ float sh_part[128 * 3];
    __shared__ float sh_cqk[DH];
    __shared__ float sh_cv[DH];

    const int tid = threadIdx.x;

    if (tid < CTXC) sh_au[tid] = audio[tid];
    __syncthreads();

    // a[c] = Wp[c,:] @ audio + bp : thread-per-c, 32 float4 contiguous
    {
        const float* wp = ctx_proj_w + ((size_t)s * C + tid) * CTXC;
        float acc = 0.f;
        #pragma unroll
        for (int k = 0; k < CTXC; k += 4) {
            float4 w = ld4(wp + k);
            float4 u = ld4(sh_au + k);
            acc += w.x * u.x + w.y * u.y + w.z * u.z + w.w * u.w;
        }
        float av = acc + ctx_proj_b[s * C + tid];
        sh_a[tid]  = av;
        sh_ap[tid] = av + pos_emb[((size_t)s * TFRAMES + (b % TFRAMES)) * C + tid];
    }
    __syncthreads();

    // cqk[d] = Wcqk[d,:] @ (a+pe), cv[d] = Wcv[d,:] @ a  (chunked, smem combine)
    {
        int chunk = tid >> 7;          // /128
        int r     = tid & 127;
        int m     = r >> 6;
        int d     = r & 63;
        const float* wrow = (m == 0 ? ctx_qk_w : ctx_v_w) + ((size_t)s * DH + d) * C + chunk * 128;
        const float* vec  = (m == 0 ? sh_ap : sh_a) + chunk * 128;
        float acc = 0.f;
        #pragma unroll
        for (int k = 0; k < 128; k += 4) {
            float4 w = ld4(wrow + k);
            float4 u = ld4(vec + k);
            acc += w.x * u.x + w.y * u.y + w.z * u.z + w.w * u.w;
        }
        sh_part[(m * 64 + d) * 3 + chunk] = acc;
    }
    __syncthreads();
    if (tid < 128) {
        float v = (sh_part[tid * 3 + 0] + sh_part[tid * 3 + 1]) + sh_part[tid * 3 + 2];
        if (tid < 64) sh_cqk[tid] = v; else sh_cv[tid - 64] = v;
    }
    __syncthreads();

    // y[c] = Wo[c,:] @ cv + bo
    {
        const float* wo = out_w + ((size_t)s * C + tid) * DH;
        float acc = 0.f;
        #pragma unroll
        for (int d = 0; d < DH; d += 4) {
            float4 w = ld4(wo + d);
            float4 t = ld4(sh_cv + d);
            acc += w.x * t.x + w.y * t.y + w.z * t.z + w.w * t.w;
        }
        g_y[(s * BT + b) * C + tid] = acc + out_b[s * C + tid];
    }

    // wq[c] = QSCALE * sum_d cqk[d] * Wqk[d,c]
    {
        float wv = 0.f;
        const float* wqk = qk_w + (size_t)s * DH * C + tid;
        #pragma unroll 16
        for (int d = 0; d < DH; d++) wv += sh_cqk[d] * wqk[(size_t)d * C];
        g_wq[(s * BT + b) * C + tid] = wv * QSCALE;
    }
}

// ---------------------------------------------------------------------------
// K2: unit = (c-chunk of 96, pixel-quad). float4 loads, streaming vout stores.
// ---------------------------------------------------------------------------
__global__ __launch_bounds__(256)
void k_sim_vout(const float* __restrict__ x0, const float* __restrict__ x1,
                const float* __restrict__ x2, const float* __restrict__ x3,
                const float* __restrict__ p0, const float* __restrict__ p1,
                const float* __restrict__ p2, const float* __restrict__ p3,
                float* __restrict__ out)
{
    int u = blockIdx.x * blockDim.x + threadIdx.x;
    if (u >= NUNITS) return;

    int chunk = u / NQUAD_TOTAL;
    int q     = u - chunk * NQUAD_TOTAL;

    int s;
    if      (q < 16000) s = 0;
    else if (q < 20000) s = 1;
    else if (q < 21000) s = 2;
    else                s = 3;

    const int hw    = c_hw[s];
    const int hw4   = c_hw4[s];
    const int local = q - c_qoff[s];
    const int b     = local / hw4;
    const int i     = (local - b * hw4) * 4;

    const float* x = (s == 0 ? x0 : s == 1 ? x1 : s == 2 ? x2 : x3);
    const float* p = (s == 0 ? p0 : s == 1 ? p1 : s == 2 ? p2 : p3);

    const int c0 = chunk * CCHUNK;
    const float* xb = x + ((size_t)b * C + c0) * hw + i;
    const float* pb = p + ((size_t)b * C + c0) * hw + i;
    const float* wq = g_wq + (s * BT + b) * C + c0;
    const float* yv = g_y  + (s * BT + b) * C + c0;
    float* vout = out + c_voutoff[s] + ((size_t)b * C + c0) * hw + i;

    float4 acc = make_float4(0.f, 0.f, 0.f, 0.f);
    #pragma unroll 4
    for (int c = 0; c < CCHUNK; c++) {
        float4 xv = ld4(xb + (size_t)c * hw);
        float4 pv = ld4(pb + (size_t)c * hw);
        float  wc = wq[c];
        acc.x = fmaf(xv.x + pv.x, wc, acc.x);
        acc.y = fmaf(xv.y + pv.y, wc, acc.y);
        acc.z = fmaf(xv.z + pv.z, wc, acc.z);
        acc.w = fmaf(xv.w + pv.w, wc, acc.w);
        float yc = yv[c];
        __stcs((float4*)(vout + (size_t)c * hw), make_float4(yc, yc, yc, yc));
    }
    int gp = c_pixoff[s] + b * hw + i;
    *(float4*)(g_simp + chunk * NPIX_TOTAL + gp) = acc;
}

// ---------------------------------------------------------------------------
// K2b: per-(s,b): reduce sim chunk partials, softmax normalize.
//   g_p[i]     = exp(sim_i - max)
//   g_srinv[sb]= 1 / sum_i exp(sim_i - max)
// ---------------------------------------------------------------------------
__global__ __launch_bounds__(256)
void k_simnorm()
{
    int s = blockIdx.x / BT;
    int b = blockIdx.x % BT;
    const int hw  = c_hw[s];
    const int off = c_pixoff[s] + b * hw;

    __shared__ float sh[6400];
    __shared__ float sh_red[8];
    __shared__ float sh_bc[2];

    const int tid  = threadIdx.x;
    const int lane = tid & 31;
    const int warp = tid >> 5;

    for (int i = tid; i < hw; i += 256) {
        int g = off + i;
        sh[i] = (g_simp[g] + g_simp[NPIX_TOTAL + g]) +
                (g_simp[2 * NPIX_TOTAL + g] + g_simp[3 * NPIX_TOTAL + g]);
    }
    __syncthreads();

    // max
    float m = -CUDART_INF_F;
    for (int i = tid; i < hw; i += 256) m = fmaxf(m, sh[i]);
    #pragma unroll
    for (int o = 16; o > 0; o >>= 1) m = fmaxf(m, __shfl_down_sync(0xffffffffu, m, o));
    if (lane == 0) sh_red[warp] = m;
    __syncthreads();
    if (tid < 8) {
        float v = sh_red[tid];
        #pragma unroll
        for (int o = 4; o > 0; o >>= 1) v = fmaxf(v, __shfl_down_sync(0xffu, v, o));
        if (tid == 0) sh_bc[0] = v;
    }
    __syncthreads();
    m = sh_bc[0];

    // exp + sum, store p
    float ssum = 0.f;
    for (int i = tid; i < hw; i += 256) {
        float e = __expf(sh[i] - m);
        g_p[off + i] = e;
        ssum += e;
    }
    ssum = warp_sum(ssum);
    if (lane == 0) sh_red[warp] = ssum;
    __syncthreads();
    if (tid < 8) {
        float v = sh_red[tid];
        #pragma unroll
        for (int o = 4; o > 0; o >>= 1) v += __shfl_down_sync(0xffu, v, o);
        if (tid == 0) g_srinv[blockIdx.x] = 1.f / v;
    }
}

// ---------------------------------------------------------------------------
// K3: xbar partials. Block = (stage, b, 16-ch group, i-segment of 1600).
// No reductions, no big smem — warp handles 2 channels, float4 path.
// ---------------------------------------------------------------------------
#define CG        16
#define NGROUPS   (C / CG)          // 24

__global__ __launch_bounds__(256)
void k_xbar(const float* __restrict__ x0, const float* __restrict__ x1,
            const float* __restrict__ x2, const float* __restrict__ x3)
{
    int blk = blockIdx.x;
    int s;
    if      (blk < 960)  s = 0;
    else if (blk < 1200) s = 1;
    else if (blk < 1440) s = 2;
    else                 s = 3;

    const int local = blk - c_xboff[s];
    const int nseg  = c_nseg[s];
    const int seg   = local % nseg;
    const int rest  = local / nseg;
    const int cg    = rest % NGROUPS;
    const int b     = rest / NGROUPS;
    const int hw    = c_hw[s];
    const int i0    = seg * ISEG;
    const int ilen  = (hw - i0 < ISEG) ? (hw - i0) : ISEG;

    const int lane = threadIdx.x & 31;
    const int warp = threadIdx.x >> 5;

    const float* x  = (s == 0 ? x0 : s == 1 ? x1 : s == 2 ? x2 : x3);
    const float* p  = g_p + c_pixoff[s] + b * hw + i0;

    const int c0 = cg * CG + warp * 2;
    const float* xc0 = x + ((size_t)b * C + c0) * hw + i0;
    const float* xc1 = xc0 + hw;

    float a00 = 0.f, a01 = 0.f, a02 = 0.f, a03 = 0.f;
    float a10 = 0.f, a11 = 0.f, a12 = 0.f, a13 = 0.f;
    for (int i = lane * 4; i < ilen; i += 128) {
        float4 pv  = ld4(p + i);
        float4 v0  = ld4(xc0 + i);
        float4 v1  = ld4(xc1 + i);
        a00 = fmaf(pv.x, v0.x, a00);
        a01 = fmaf(pv.y, v0.y, a01);
        a02 = fmaf(pv.z, v0.z, a02);
        a03 = fmaf(pv.w, v0.w, a03);
        a10 = fmaf(pv.x, v1.x, a10);
        a11 = fmaf(pv.y, v1.y, a11);
        a12 = fmaf(pv.z, v1.z, a12);
        a13 = fmaf(pv.w, v1.w, a13);
    }
    float r0 = warp_sum((a00 + a01) + (a02 + a03));
    float r1 = warp_sum((a10 + a11) + (a12 + a13));
    if (lane == 0) {
        int base = seg * (NSTG * BT * C) + (s * BT + b) * C + c0;
        g_xbarp[base]     = r0;
        g_xbarp[base + 1] = r1;
    }
}

// ---------------------------------------------------------------------------
// K4: combine xbar partials (fixed order), then aout = bco + Wco@(Wv@xbar).
// ---------------------------------------------------------------------------
__global__ __launch_bounds__(C)
void k_aout(const float* __restrict__ v_w,
            const float* __restrict__ ctx_out_w,
            const float* __restrict__ ctx_out_b,
            float* __restrict__ out)
{
    int s = blockIdx.x / BT;
    int b = blockIdx.x % BT;
    __shared__ float sh_xb[C];
    __shared__ float sh_part[DH * 6];
    __shared__ float sh_t[DH];

    const int tid = threadIdx.x;
    const int sb  = s * BT + b;

    // combine segment partials, normalize
    {
        float rinv = g_srinv[sb];
        int idx = sb * C + tid;
        float v = g_xbarp[idx];
        if (s == 0) {
            v = (v + g_xbarp[NSTG * BT * C + idx]) +
                (g_xbarp[2 * NSTG * BT * C + idx] + g_xbarp[3 * NSTG * BT * C + idx]);
        }
        sh_xb[tid] = v * rinv;
    }
    __syncthreads();

    // t[d] = Wv[d,:] @ xbar  (64-float segments per thread, smem combine)
    {
        int chunk = tid >> 6;
        int d     = tid & 63;
        const float* wv  = v_w + ((size_t)s * DH + d) * C + chunk * 64;
        const float* vec = sh_xb + chunk * 64;
        float acc = 0.f;
        #pragma unroll
        for (int k = 0; k < 64; k += 4) {
            float4 w = ld4(wv + k);
            float4 u = ld4(vec + k);
            acc += w.x * u.x + w.y * u.y + w.z * u.z + w.w * u.w;
        }
        sh_part[d * 6 + chunk] = acc;
    }
    __syncthreads();
    if (tid < DH) {
        const float* pp = sh_part + tid * 6;
        sh_t[tid] = ((pp[0] + pp[1]) + (pp[2] + pp[3])) + (pp[4] + pp[5]);
    }
    __syncthreads();

    // aout[c] = Wco[c,:] @ t + bco
    {
        const float* wco = ctx_out_w + ((size_t)s * C + tid) * DH;
        float acc = 0.f;
        #pragma unroll
        for (int d = 0; d < DH; d += 4) {
            float4 w = ld4(wco + d);
            float4 t = ld4(sh_t + d);
            acc += w.x * t.x + w.y * t.y + w.z * t.z + w.w * t.w;
        }
        out[VOUT_TOTAL + sb * C + tid] = acc + ctx_out_b[s * C + tid];
    }
}

// ---------------------------------------------------------------------------
extern "C" void kernel_launch(void* const* d_in, const int* in_sizes, int n_in,
                              void* d_out, int out_size)
{
    const float *fm[NSTG], *ps[NSTG], *au[NSTG];
    bool dict_order = (in_sizes[1] == in_sizes[0]);
    if (dict_order) {
        for (int s = 0; s < NSTG; s++) {
            fm[s] = (const float*)d_in[3 * s + 0];
            ps[s] = (const float*)d_in[3 * s + 1];
            au[s] = (const float*)d_in[3 * s + 2];
        }
    } else {
        for (int s = 0; s < NSTG; s++) {
            fm[s] = (const float*)d_in[s];
            au[s] = (const float*)d_in[4 + s];
            ps[s] = (const float*)d_in[8 + s];
        }
    }
    const float* ctx_proj_w = (const float*)d_in[12];
    const float* ctx_proj_b = (const float*)d_in[13];
    const float* pos_emb    = (const float*)d_in[14];
    const float* qk_w       = (const float*)d_in[15];
    const float* ctx_qk_w   = (const float*)d_in[16];
    const float* v_w        = (const float*)d_in[17];
    const float* ctx_v_w    = (const float*)d_in[18];
    const float* out_w      = (const float*)d_in[19];
    const float* out_b      = (const float*)d_in[20];
    const float* ctx_out_w  = (const float*)d_in[21];
    const float* ctx_out_b  = (const float*)d_in[22];

    float* out = (float*)d_out;

    k_setup<<<NSTG * BT, C>>>(au[0], au[1], au[2], au[3],
                              ctx_proj_w, ctx_proj_b, pos_emb,
                              qk_w, ctx_qk_w, ctx_v_w, out_w, out_b);

    k_sim_vout<<<(NUNITS + 255) / 256, 256>>>(fm[0], fm[1], fm[2], fm[3],
                                              ps[0], ps[1], ps[2], ps[3], out);

    k_simnorm<<<NSTG * BT, 256>>>();

    k_xbar<<<XBAR_BLOCKS, 256>>>(fm[0], fm[1], fm[2], fm[3]);

    k_aout<<<NSTG * BT, C>>>(v_w, ctx_out_w, ctx_out_b, out);
}